// round 15
// baseline (speedup 1.0000x reference)
#include <cuda_runtime.h>
#include <cuda_fp16.h>
#include <math.h>
#include <stdint.h>

#define Nn 20000
#define Ee 320000
#define Ff 128
#define EPS 1e-5f

#define EPB 128
#define THREADS 512
#define TILES (Ee / EPB)       // 2500
#define EDGE_GRID 148

// edge kernel smem layout (bytes)
#define OFF_W2 0               // 4 panels x 32768 (256 rows x 128B, SW128) = 128K resident
#define OFF_H1 131072          // 4 panels x 16384 (128 rows x 128B) = 64K (h1, then h2)
#define OFF_W3 196608          // 2 chunk buffers x 16384 (128 rows x 128B)
#define EDGESMEM 229376

#define SWZ(x) ((x) ^ (((x) >> 3) & 0x70))

// ---- device scratch ----
__device__ __half  d_Ch[512 * 128];          // folded layer-1 weights (fp16)
__device__ __half  d_W2h[256 * 256];
__device__ __half  d_W3h[128 * 256];
__device__ float   d_b2f[256];
__device__ __half2 d_b1h2[128];
__device__ __half  d_UVh[(size_t)Nn * 512];
__device__ float   d_sum[(size_t)Nn * Ff];
__device__ float   d_cnt[Nn];

__device__ __forceinline__ void mma16(float d[4], const uint32_t a[4], const uint32_t b[2]) {
    asm volatile(
        "mma.sync.aligned.m16n8k16.row.col.f32.f16.f16.f32 "
        "{%0,%1,%2,%3}, {%4,%5,%6,%7}, {%8,%9}, {%0,%1,%2,%3};\n"
        : "+f"(d[0]), "+f"(d[1]), "+f"(d[2]), "+f"(d[3])
        : "r"(a[0]), "r"(a[1]), "r"(a[2]), "r"(a[3]), "r"(b[0]), "r"(b[1]));
}
__device__ __forceinline__ void ldsm4(uint32_t r[4], uint32_t addr) {
    asm volatile("ldmatrix.sync.aligned.m8n8.x4.shared.b16 {%0,%1,%2,%3}, [%4];"
                 : "=r"(r[0]), "=r"(r[1]), "=r"(r[2]), "=r"(r[3]) : "r"(addr));
}
__device__ __forceinline__ uint32_t smem_u32(const void* p) {
    uint32_t a;
    asm("{ .reg .u64 t; cvta.to.shared.u64 t, %1; cvt.u32.u64 %0, t; }" : "=r"(a) : "l"(p));
    return a;
}

// ---------------------------------------------------------------
__global__ void zero_kernel() {
    int i = blockIdx.x * blockDim.x + threadIdx.x;
    if (i < Nn * Ff / 4) ((float4*)d_sum)[i] = make_float4(0.f, 0.f, 0.f, 0.f);
    if (i < Nn / 4)      ((float4*)d_cnt)[i] = make_float4(0.f, 0.f, 0.f, 0.f);
}

__global__ void prep_kernel(const float* __restrict__ W1, const float* __restrict__ b1,
                            const float* __restrict__ g1, const float* __restrict__ be1,
                            const float* __restrict__ rm1, const float* __restrict__ rv1,
                            const float* __restrict__ W2, const float* __restrict__ b2,
                            const float* __restrict__ g2, const float* __restrict__ be2,
                            const float* __restrict__ rm2, const float* __restrict__ rv2,
                            const float* __restrict__ W3) {
    int i = blockIdx.x * blockDim.x + threadIdx.x;
    if (i < 512 * 128) {
        int j = i >> 7, k = i & 127, o = j & 255;
        float s = g1[o] * rsqrtf(rv1[o] + EPS);
        float w = (j < 256) ? (W1[o * 256 + k] - W1[o * 256 + 128 + k])
                            : W1[o * 256 + 128 + k];
        d_Ch[i] = __float2half(s * w);
    }
    if (i < 256 * 256) {
        int o = i >> 8;
        float s = g2[o] * rsqrtf(rv2[o] + EPS);
        d_W2h[i] = __float2half(s * W2[i]);
    }
    if (i < 128 * 256) d_W3h[i] = __float2half(W3[i]);
    if (i < 256) {
        float s2v = g2[i] * rsqrtf(rv2[i] + EPS);
        d_b2f[i] = b2[i] * s2v + (be2[i] - rm2[i] * s2v);
    }
    if (i < 128) {
        int o0 = 2 * i, o1 = 2 * i + 1;
        float sa = g1[o0] * rsqrtf(rv1[o0] + EPS);
        float sb = g1[o1] * rsqrtf(rv1[o1] + EPS);
        d_b1h2[i] = __floats2half2_rn(b1[o0] * sa + (be1[o0] - rm1[o0] * sa),
                                      b1[o1] * sb + (be1[o1] - rm1[o1] * sb));
    }
}

// UV = x @ C^T via fp16 mma (fp32 accum). grid (313, 2), 2 CTAs/SM.
#define SXH2 68
#define UVSMEM ((64 + 256) * SXH2 * 4)
__global__ __launch_bounds__(256, 2) void uv_gemm(const float* __restrict__ x) {
    extern __shared__ __half2 smh[];
    __half2* xs2 = smh;                 // [64][SXH2]
    __half2* cs2 = smh + 64 * SXH2;     // [256][SXH2]
    const __half* xsh = (const __half*)xs2;
    const __half* csh = (const __half*)cs2;
    int t = threadIdx.x, lane = t & 31, wid = t >> 5;
    int rowBase = blockIdx.x * 64;
    int cb = blockIdx.y * 256;

#pragma unroll
    for (int j = 0; j < 8; ++j) {
        int idx = t + j * 256;
        int r = idx >> 5, c4 = idx & 31;
        int gr = rowBase + r;
        float4 v = (gr < Nn) ? *(const float4*)(x + (size_t)gr * 128 + c4 * 4)
                             : make_float4(0.f, 0.f, 0.f, 0.f);
        xs2[r * SXH2 + c4 * 2]     = __floats2half2_rn(v.x, v.y);
        xs2[r * SXH2 + c4 * 2 + 1] = __floats2half2_rn(v.z, v.w);
    }
#pragma unroll
    for (int j = 0; j < 16; ++j) {
        int idx = t + j * 256;
        int n = idx >> 4, c8 = idx & 15;
        uint4 w = *(const uint4*)(d_Ch + (size_t)(cb + n) * 128 + c8 * 8);
        *(uint4*)((__half*)(cs2 + n * SXH2) + c8 * 8) = w;
    }
    __syncthreads();

    int warpM = wid >> 2, warpN = wid & 3;
    int rB = warpM * 32, cB = warpN * 64;
    int qr = lane >> 2, qc = lane & 3;

    float acc[2][8][4] = {};
#pragma unroll
    for (int ks = 0; ks < 8; ++ks) {
        int kg = ks * 16;
        uint32_t a[2][4];
#pragma unroll
        for (int mi = 0; mi < 2; ++mi) {
            int r0 = rB + mi * 16 + qr;
            a[mi][0] = *(const uint32_t*)(xsh + r0 * (2 * SXH2) + kg + 2 * qc);
            a[mi][1] = *(const uint32_t*)(xsh + (r0 + 8) * (2 * SXH2) + kg + 2 * qc);
            a[mi][2] = *(const uint32_t*)(xsh + r0 * (2 * SXH2) + kg + 8 + 2 * qc);
            a[mi][3] = *(const uint32_t*)(xsh + (r0 + 8) * (2 * SXH2) + kg + 8 + 2 * qc);
        }
#pragma unroll
        for (int ni = 0; ni < 8; ++ni) {
            int n0 = cB + ni * 8 + qr;
            uint32_t b[2];
            b[0] = *(const uint32_t*)(csh + n0 * (2 * SXH2) + kg + 2 * qc);
            b[1] = *(const uint32_t*)(csh + n0 * (2 * SXH2) + kg + 8 + 2 * qc);
            mma16(acc[0][ni], a[0], b);
            mma16(acc[1][ni], a[1], b);
        }
    }
#pragma unroll
    for (int mi = 0; mi < 2; ++mi)
#pragma unroll
        for (int ni = 0; ni < 8; ++ni) {
            int r0 = rowBase + rB + mi * 16 + qr;
            int c0 = cb + cB + ni * 8 + 2 * qc;
            if (r0 < Nn)
                *(__half2*)(d_UVh + (size_t)r0 * 512 + c0) =
                    __floats2half2_rn(acc[mi][ni][0], acc[mi][ni][1]);
            if (r0 + 8 < Nn)
                *(__half2*)(d_UVh + (size_t)(r0 + 8) * 512 + c0) =
                    __floats2half2_rn(acc[mi][ni][2], acc[mi][ni][3]);
        }
}

// ---- persistent fused edge MLP: ldmatrix fragments, W2 resident, W3 streamed ----
// edge_index is int32 on the wire. src=ei[i], dst=ei[E+i]. Degree counting fused
// into the scatter. Layer-3 A fragments for a warp's own K-chunk (kc == warpN)
// come straight from the layer-2 accumulator registers (identical lane layout).
__global__ __launch_bounds__(THREADS, 1) void edge_kernel(const int* __restrict__ ei,
                                                          const float* __restrict__ b3) {
    extern __shared__ char smem[];
    uint32_t sb = smem_u32(smem);
    int t = threadIdx.x, lane = t & 31, wid = t >> 5;

    // ---- load W2 into 4 swizzled panels (once per CTA) ----
#pragma unroll
    for (int j = 0; j < 16; ++j) {
        int item = j * THREADS + t;              // 8192 items
        int r = item >> 5, p = (item >> 3) & 3, ch = item & 7;
        uint4 w = *(const uint4*)(d_W2h + (size_t)r * 256 + p * 64 + ch * 8);
        *(uint4*)(smem + OFF_W2 + p * 32768 + SWZ(r * 128 + ch * 16)) = w;
    }

    int warpM = wid >> 2, warpN = wid & 3;       // 4x4 warp grid
    int qr = lane >> 2, qc = lane & 3;
    uint32_t xorl = (uint32_t)(lane & 7) << 4;   // SW128 XOR for ldmatrix rows
    uint32_t xorq = (uint32_t)qr << 4;           // SW128 XOR for epilogue rows
    const __half2 z2 = __float2half2_rn(0.f);

    // ldmatrix per-lane bases
    uint32_t aColHi = ((lane >> 4) & 1) * 16;
    uint32_t aBase  = sb + OFF_H1 + (warpM * 32 + (lane & 15)) * 128;
    uint32_t bRowOff = (uint32_t)((lane & 7) + ((lane >> 4) << 3));
    uint32_t bColHi  = ((lane >> 3) & 1) * 16;
    uint32_t b2Base  = sb + OFF_W2 + (warpN * 64 + bRowOff) * 128;
    uint32_t b3Base  = sb + OFF_W3 + (warpN * 32 + bRowOff) * 128;

    // W3 chunk-stream item coords (per thread, 2 items of 16B per chunk)
    int w3n0 = t >> 3, w3ch = t & 7;
    int w3n1 = (512 + t) >> 3;
    uint32_t w3soff0 = SWZ(w3n0 * 128 + w3ch * 16);
    uint32_t w3soff1 = SWZ(w3n1 * 128 + w3ch * 16);

    for (int tile = blockIdx.x; tile < TILES; tile += gridDim.x) {
        int e0 = tile * EPB;
        __syncthreads();   // h1 free: prev tile's layer-3 reads done

        // ---- gather + layer-1 -> h1 panels (fp16, swizzled), 128 edges ----
#pragma unroll
        for (int j = 0; j < 8; ++j) {
            int item = j * THREADS + t;          // 4096 items
            int e = item >> 5, p = (item >> 3) & 3, ch = item & 7;
            int sidx = __ldg(ei + e0 + e);
            int didx = __ldg(ei + Ee + e0 + e);
            uint4 uu = *(const uint4*)(d_UVh + (size_t)didx * 512 + p * 64 + ch * 8);
            uint4 vv = *(const uint4*)(d_UVh + (size_t)sidx * 512 + 256 + p * 64 + ch * 8);
            const __half2* up = (const __half2*)&uu;
            const __half2* vp = (const __half2*)&vv;
            __half2 r[4];
#pragma unroll
            for (int q = 0; q < 4; ++q)
                r[q] = __hmax2(__hadd2(__hadd2(up[q], vp[q]), d_b1h2[p * 32 + ch * 4 + q]), z2);
            *(uint4*)(smem + OFF_H1 + p * 16384 + SWZ(e * 128 + ch * 16)) = *(uint4*)r;
        }
        __syncthreads();

        // ---- layer 2: [128,256] = h1 @ W2^T, warp tile 32x64, ldmatrix frags ----
        uint32_t ownA[2][4][4];   // layer-3 A frags for own kc (== warpN), built in epilogue
        {
            float acc[2][8][4] = {};
#pragma unroll
            for (int ks = 0; ks < 16; ++ks) {
                int kg = ks * 16, p = kg >> 6;
                uint32_t kp2 = (uint32_t)((kg & 63) * 2);
                uint32_t a0[4], a1[4];
                uint32_t acb = (kp2 + aColHi) ^ xorl;
                ldsm4(a0, aBase + p * 16384 + acb);
                ldsm4(a1, aBase + 2048 + p * 16384 + acb);
                uint32_t wb = b2Base + p * 32768 + ((kp2 + bColHi) ^ xorl);
#pragma unroll
                for (int ni2 = 0; ni2 < 4; ++ni2) {
                    uint32_t bb[4];
                    ldsm4(bb, wb + ni2 * 2048);
                    mma16(acc[0][2 * ni2],     a0, bb);
                    mma16(acc[1][2 * ni2],     a1, bb);
                    mma16(acc[0][2 * ni2 + 1], a0, bb + 2);
                    mma16(acc[1][2 * ni2 + 1], a1, bb + 2);
                }
            }

            // prefetch W3 chunks 0,1 (LDG into regs; STS after sync)
            uint4 wA0 = *(const uint4*)(d_W3h + (size_t)w3n0 * 256 + 0 * 64 + w3ch * 8);
            uint4 wA1 = *(const uint4*)(d_W3h + (size_t)w3n1 * 256 + 0 * 64 + w3ch * 8);
            uint4 wB0 = *(const uint4*)(d_W3h + (size_t)w3n0 * 256 + 1 * 64 + w3ch * 8);
            uint4 wB1 = *(const uint4*)(d_W3h + (size_t)w3n1 * 256 + 1 * 64 + w3ch * 8);

            __syncthreads();   // all layer-2 reads of h1 done

            // ---- bias + relu + fp16: h2 over h1 panels; capture ownA; stage W3 0,1 ----
            {
                int rB = warpM * 32, cB = warpN * 64;
#pragma unroll
                for (int mi = 0; mi < 2; ++mi) {
                    int r0 = rB + mi * 16 + qr, r1 = r0 + 8;
#pragma unroll
                    for (int ni = 0; ni < 8; ++ni) {
                        int c0 = cB + ni * 8 + 2 * qc;
                        int p = c0 >> 6, cp = c0 & 63;
                        float2 bb = __ldg((const float2*)(d_b2f + c0));
                        char* hp = smem + OFF_H1 + p * 16384;
                        uint32_t coff = ((uint32_t)(cp * 2)) ^ xorq;
                        __half2 hlo = __floats2half2_rn(fmaxf(acc[mi][ni][0] + bb.x, 0.f),
                                                        fmaxf(acc[mi][ni][1] + bb.y, 0.f));
                        __half2 hhi = __floats2half2_rn(fmaxf(acc[mi][ni][2] + bb.x, 0.f),
                                                        fmaxf(acc[mi][ni][3] + bb.y, 0.f));
                        *(__half2*)(hp + r0 * 128 + coff) = hlo;
                        *(__half2*)(hp + r1 * 128 + coff) = hhi;
                        // ownA[mi][ks][*]: ks = ni>>1; even ni -> slots 0,1; odd -> 2,3
                        ownA[mi][ni >> 1][(ni & 1) * 2]     = *(uint32_t*)&hlo;
                        ownA[mi][ni >> 1][(ni & 1) * 2 + 1] = *(uint32_t*)&hhi;
                    }
                }
                *(uint4*)(smem + OFF_W3 + w3soff0) = wA0;
                *(uint4*)(smem + OFF_W3 + w3soff1) = wA1;
                *(uint4*)(smem + OFF_W3 + 16384 + w3soff0) = wB0;
                *(uint4*)(smem + OFF_W3 + 16384 + w3soff1) = wB1;
            }
        }
        // prefetch W3 chunks 2,3
        uint4 wA0 = *(const uint4*)(d_W3h + (size_t)w3n0 * 256 + 2 * 64 + w3ch * 8);
        uint4 wA1 = *(const uint4*)(d_W3h + (size_t)w3n1 * 256 + 2 * 64 + w3ch * 8);
        uint4 wB0 = *(const uint4*)(d_W3h + (size_t)w3n0 * 256 + 3 * 64 + w3ch * 8);
        uint4 wB1 = *(const uint4*)(d_W3h + (size_t)w3n1 * 256 + 3 * 64 + w3ch * 8);

        __syncthreads();   // h2 + W3 chunks 0,1 visible

        // ---- layer 3: [128,128] = h2 @ W3^T, warp tile 32x32 ----
        float acc3[2][4][4] = {};
#pragma unroll
        for (int kc = 0; kc < 2; ++kc) {
            uint32_t wb3 = b3Base + kc * 16384;
            uint32_t ab3 = aBase + kc * 16384;          // A panel = kc
            bool own = (warpN == kc);
#pragma unroll
            for (int ks = 0; ks < 4; ++ks) {
                uint32_t kp2 = (uint32_t)(ks * 32);
                uint32_t a0[4], a1[4];
                if (own) {
#pragma unroll
                    for (int q = 0; q < 4; ++q) { a0[q] = ownA[0][ks][q]; a1[q] = ownA[1][ks][q]; }
                } else {
                    uint32_t acb = (kp2 + aColHi) ^ xorl;
                    ldsm4(a0, ab3 + acb);
                    ldsm4(a1, ab3 + 2048 + acb);
                }
                uint32_t wb = wb3 + ((kp2 + bColHi) ^ xorl);
#pragma unroll
                for (int ni2 = 0; ni2 < 2; ++ni2) {
                    uint32_t bb[4];
                    ldsm4(bb, wb + ni2 * 2048);
                    mma16(acc3[0][2 * ni2],     a0, bb);
                    mma16(acc3[1][2 * ni2],     a1, bb);
                    mma16(acc3[0][2 * ni2 + 1], a0, bb + 2);
                    mma16(acc3[1][2 * ni2 + 1], a1, bb + 2);
                }
            }
        }
        __syncthreads();   // chunk buffers 0,1 consumed
        *(uint4*)(smem + OFF_W3 + w3soff0) = wA0;
        *(uint4*)(smem + OFF_W3 + w3soff1) = wA1;
        *(uint4*)(smem + OFF_W3 + 16384 + w3soff0) = wB0;
        *(uint4*)(smem + OFF_W3 + 16384 + w3soff1) = wB1;
        __syncthreads();   // chunks 2,3 staged
#pragma unroll
        for (int kc = 0; kc < 2; ++kc) {
            uint32_t wb3 = b3Base + kc * 16384;
            uint32_t ab3 = aBase + (2 + kc) * 16384;    // A panel = 2+kc
            bool own = (warpN == 2 + kc);
#pragma unroll
            for (int ks = 0; ks < 4; ++ks) {
                uint32_t kp2 = (uint32_t)(ks * 32);
                uint32_t a0[4], a1[4];
                if (own) {
#pragma unroll
                    for (int q = 0; q < 4; ++q) { a0[q] = ownA[0][ks][q]; a1[q] = ownA[1][ks][q]; }
                } else {
                    uint32_t acb = (kp2 + aColHi) ^ xorl;
                    ldsm4(a0, ab3 + acb);
                    ldsm4(a1, ab3 + 2048 + acb);
                }
                uint32_t wb = wb3 + ((kp2 + bColHi) ^ xorl);
#pragma unroll
                for (int ni2 = 0; ni2 < 2; ++ni2) {
                    uint32_t bb[4];
                    ldsm4(bb, wb + ni2 * 2048);
                    mma16(acc3[0][2 * ni2],     a0, bb);
                    mma16(acc3[1][2 * ni2],     a1, bb);
                    mma16(acc3[0][2 * ni2 + 1], a0, bb + 2);
                    mma16(acc3[1][2 * ni2 + 1], a1, bb + 2);
                }
            }
        }

        // ---- scatter: bias + vector atomics into d_sum[dst]; fused degree count ----
        int rB = warpM * 32, cB3 = warpN * 32;
#pragma unroll
        for (int mi = 0; mi < 2; ++mi) {
            int r0 = rB + mi * 16 + qr;
            int d0 = __ldg(ei + Ee + e0 + r0);
            int d1 = __ldg(ei + Ee + e0 + r0 + 8);
            float* p0b = d_sum + (size_t)d0 * Ff;
            float* p1b = d_sum + (size_t)d1 * Ff;
            if (warpN == 0 && qc == 0) {
                asm volatile("red.global.add.f32 [%0], %1;" :: "l"(d_cnt + d0), "f"(1.0f) : "memory");
                asm volatile("red.global.add.f32 [%0], %1;" :: "l"(d_cnt + d1), "f"(1.0f) : "memory");
            }
#pragma unroll
            for (int ni = 0; ni < 4; ++ni) {
                int c0 = cB3 + ni * 8 + 2 * qc;
                float2 bb = __ldg((const float2*)(b3 + c0));
                asm volatile("red.global.add.v2.f32 [%0], {%1,%2};"
                             :: "l"(p0b + c0), "f"(acc3[mi][ni][0] + bb.x),
                                "f"(acc3[mi][ni][1] + bb.y) : "memory");
                asm volatile("red.global.add.v2.f32 [%0], {%1,%2};"
                             :: "l"(p1b + c0), "f"(acc3[mi][ni][2] + bb.x),
                                "f"(acc3[mi][ni][3] + bb.y) : "memory");
            }
        }
    }
}

__global__ void final_kernel(float* __restrict__ out) {
    int i = blockIdx.x * blockDim.x + threadIdx.x;
    if (i < Nn * Ff / 4) {
        int n = i >> 5;
        float c = fmaxf(d_cnt[n], 1.0f);
        float4 v = ((const float4*)d_sum)[i];
        ((float4*)out)[i] = make_float4(tanhf(v.x / c), tanhf(v.y / c),
                                        tanhf(v.z / c), tanhf(v.w / c));
    }
}

// ---------------------------------------------------------------
extern "C" void kernel_launch(void* const* d_in, const int* in_sizes, int n_in,
                              void* d_out, int out_size) {
    const float* x  = (const float*)d_in[0];
    const int*   ei = (const int*)d_in[1];     // int32 (JAX x64 disabled)
    const float* W1 = (const float*)d_in[2];
    const float* b1 = (const float*)d_in[3];
    const float* g1 = (const float*)d_in[4];
    const float* be1 = (const float*)d_in[5];
    const float* rm1 = (const float*)d_in[6];
    const float* rv1 = (const float*)d_in[7];
    const float* W2 = (const float*)d_in[8];
    const float* b2 = (const float*)d_in[9];
    const float* g2 = (const float*)d_in[10];
    const float* be2 = (const float*)d_in[11];
    const float* rm2 = (const float*)d_in[12];
    const float* rv2 = (const float*)d_in[13];
    const float* W3 = (const float*)d_in[14];
    const float* b3 = (const float*)d_in[15];
    float* out = (float*)d_out;

    cudaFuncSetAttribute(uv_gemm, cudaFuncAttributeMaxDynamicSharedMemorySize, UVSMEM);
    cudaFuncSetAttribute(edge_kernel, cudaFuncAttributeMaxDynamicSharedMemorySize, EDGESMEM);

    zero_kernel<<<(Nn * Ff / 4 + 255) / 256, 256>>>();
    prep_kernel<<<(512 * 128 + 255) / 256, 256>>>(W1, b1, g1, be1, rm1, rv1,
                                                  W2, b2, g2, be2, rm2, rv2, W3);
    uv_gemm<<<dim3((Nn + 63) / 64, 2), 256, UVSMEM>>>(x);
    edge_kernel<<<EDGE_GRID, THREADS, EDGESMEM>>>(ei, b3);
    final_kernel<<<(Nn * Ff / 4 + 255) / 256, 256>>>(out);
}

// round 16
// speedup vs baseline: 1.0534x; 1.0534x over previous
#include <cuda_runtime.h>
#include <cuda_fp16.h>
#include <math.h>
#include <stdint.h>

#define Nn 20000
#define Ee 320000
#define Ff 128
#define EPS 1e-5f

#define EPB 128
#define THREADS 512
#define TILES (Ee / EPB)       // 2500
#define EDGE_GRID 148

// edge kernel smem layout (bytes)
#define OFF_W2 0               // 4 panels x 32768 (256 rows x 128B, SW128) = 128K resident
#define OFF_H1 131072          // 4 panels x 16384 (128 rows x 128B) = 64K (h1, then h2)
#define OFF_W3 196608          // 2 chunk buffers x 16384 (128 rows x 128B), ping-pong pairs
#define EDGESMEM 229376

#define SWZ(x) ((x) ^ (((x) >> 3) & 0x70))

// ---- device scratch ----
__device__ __half  d_Ch[512 * 128];          // folded layer-1 weights (fp16)
__device__ __half  d_W2h[256 * 256];
__device__ __half  d_W3h[128 * 256];
__device__ __half2 d_b2h2[128];
__device__ __half2 d_b1h2[128];
__device__ __half  d_UVh[(size_t)Nn * 512];
__device__ float   d_sum[(size_t)Nn * Ff];
__device__ float   d_cnt[Nn];

__device__ __forceinline__ void mma16(float d[4], const uint32_t a[4], const uint32_t b[2]) {
    asm volatile(
        "mma.sync.aligned.m16n8k16.row.col.f32.f16.f16.f32 "
        "{%0,%1,%2,%3}, {%4,%5,%6,%7}, {%8,%9}, {%0,%1,%2,%3};\n"
        : "+f"(d[0]), "+f"(d[1]), "+f"(d[2]), "+f"(d[3])
        : "r"(a[0]), "r"(a[1]), "r"(a[2]), "r"(a[3]), "r"(b[0]), "r"(b[1]));
}
__device__ __forceinline__ void ldsm4(uint32_t r[4], uint32_t addr) {
    asm volatile("ldmatrix.sync.aligned.m8n8.x4.shared.b16 {%0,%1,%2,%3}, [%4];"
                 : "=r"(r[0]), "=r"(r[1]), "=r"(r[2]), "=r"(r[3]) : "r"(addr));
}
__device__ __forceinline__ uint32_t smem_u32(const void* p) {
    uint32_t a;
    asm("{ .reg .u64 t; cvta.to.shared.u64 t, %1; cvt.u32.u64 %0, t; }" : "=r"(a) : "l"(p));
    return a;
}

// ---------------------------------------------------------------
// prep + zero fused: grid covers max(weight work, zero work)
__global__ void prep_kernel(const float* __restrict__ W1, const float* __restrict__ b1,
                            const float* __restrict__ g1, const float* __restrict__ be1,
                            const float* __restrict__ rm1, const float* __restrict__ rv1,
                            const float* __restrict__ W2, const float* __restrict__ b2,
                            const float* __restrict__ g2, const float* __restrict__ be2,
                            const float* __restrict__ rm2, const float* __restrict__ rv2,
                            const float* __restrict__ W3) {
    int i = blockIdx.x * blockDim.x + threadIdx.x;
    if (i < Nn * Ff / 4) ((float4*)d_sum)[i] = make_float4(0.f, 0.f, 0.f, 0.f);
    if (i < Nn / 4)      ((float4*)d_cnt)[i] = make_float4(0.f, 0.f, 0.f, 0.f);
    if (i < 512 * 128) {
        int j = i >> 7, k = i & 127, o = j & 255;
        float s = g1[o] * rsqrtf(rv1[o] + EPS);
        float w = (j < 256) ? (W1[o * 256 + k] - W1[o * 256 + 128 + k])
                            : W1[o * 256 + 128 + k];
        d_Ch[i] = __float2half(s * w);
    }
    if (i < 256 * 256) {
        int o = i >> 8;
        float s = g2[o] * rsqrtf(rv2[o] + EPS);
        d_W2h[i] = __float2half(s * W2[i]);
    }
    if (i < 128 * 256) d_W3h[i] = __float2half(W3[i]);
    if (i < 128) {
        int o0 = 2 * i, o1 = 2 * i + 1;
        float s0 = g2[o0] * rsqrtf(rv2[o0] + EPS);
        float s1 = g2[o1] * rsqrtf(rv2[o1] + EPS);
        d_b2h2[i] = __floats2half2_rn(b2[o0] * s0 + (be2[o0] - rm2[o0] * s0),
                                      b2[o1] * s1 + (be2[o1] - rm2[o1] * s1));
        float sa = g1[o0] * rsqrtf(rv1[o0] + EPS);
        float sb = g1[o1] * rsqrtf(rv1[o1] + EPS);
        d_b1h2[i] = __floats2half2_rn(b1[o0] * sa + (be1[o0] - rm1[o0] * sa),
                                      b1[o1] * sb + (be1[o1] - rm1[o1] * sb));
    }
}

// UV = x @ C^T via fp16 mma (fp32 accum). grid (313, 2), 2 CTAs/SM.
#define SXH2 68
#define UVSMEM ((64 + 256) * SXH2 * 4)
__global__ __launch_bounds__(256, 2) void uv_gemm(const float* __restrict__ x) {
    extern __shared__ __half2 smh[];
    __half2* xs2 = smh;                 // [64][SXH2]
    __half2* cs2 = smh + 64 * SXH2;     // [256][SXH2]
    const __half* xsh = (const __half*)xs2;
    const __half* csh = (const __half*)cs2;
    int t = threadIdx.x, lane = t & 31, wid = t >> 5;
    int rowBase = blockIdx.x * 64;
    int cb = blockIdx.y * 256;

#pragma unroll
    for (int j = 0; j < 8; ++j) {
        int idx = t + j * 256;
        int r = idx >> 5, c4 = idx & 31;
        int gr = rowBase + r;
        float4 v = (gr < Nn) ? *(const float4*)(x + (size_t)gr * 128 + c4 * 4)
                             : make_float4(0.f, 0.f, 0.f, 0.f);
        xs2[r * SXH2 + c4 * 2]     = __floats2half2_rn(v.x, v.y);
        xs2[r * SXH2 + c4 * 2 + 1] = __floats2half2_rn(v.z, v.w);
    }
#pragma unroll
    for (int j = 0; j < 16; ++j) {
        int idx = t + j * 256;
        int n = idx >> 4, c8 = idx & 15;
        uint4 w = *(const uint4*)(d_Ch + (size_t)(cb + n) * 128 + c8 * 8);
        *(uint4*)((__half*)(cs2 + n * SXH2) + c8 * 8) = w;
    }
    __syncthreads();

    int warpM = wid >> 2, warpN = wid & 3;
    int rB = warpM * 32, cB = warpN * 64;
    int qr = lane >> 2, qc = lane & 3;

    float acc[2][8][4] = {};
#pragma unroll
    for (int ks = 0; ks < 8; ++ks) {
        int kg = ks * 16;
        uint32_t a[2][4];
#pragma unroll
        for (int mi = 0; mi < 2; ++mi) {
            int r0 = rB + mi * 16 + qr;
            a[mi][0] = *(const uint32_t*)(xsh + r0 * (2 * SXH2) + kg + 2 * qc);
            a[mi][1] = *(const uint32_t*)(xsh + (r0 + 8) * (2 * SXH2) + kg + 2 * qc);
            a[mi][2] = *(const uint32_t*)(xsh + r0 * (2 * SXH2) + kg + 8 + 2 * qc);
            a[mi][3] = *(const uint32_t*)(xsh + (r0 + 8) * (2 * SXH2) + kg + 8 + 2 * qc);
        }
#pragma unroll
        for (int ni = 0; ni < 8; ++ni) {
            int n0 = cB + ni * 8 + qr;
            uint32_t b[2];
            b[0] = *(const uint32_t*)(csh + n0 * (2 * SXH2) + kg + 2 * qc);
            b[1] = *(const uint32_t*)(csh + n0 * (2 * SXH2) + kg + 8 + 2 * qc);
            mma16(acc[0][ni], a[0], b);
            mma16(acc[1][ni], a[1], b);
        }
    }
#pragma unroll
    for (int mi = 0; mi < 2; ++mi)
#pragma unroll
        for (int ni = 0; ni < 8; ++ni) {
            int r0 = rowBase + rB + mi * 16 + qr;
            int c0 = cb + cB + ni * 8 + 2 * qc;
            if (r0 < Nn)
                *(__half2*)(d_UVh + (size_t)r0 * 512 + c0) =
                    __floats2half2_rn(acc[mi][ni][0], acc[mi][ni][1]);
            if (r0 + 8 < Nn)
                *(__half2*)(d_UVh + (size_t)(r0 + 8) * 512 + c0) =
                    __floats2half2_rn(acc[mi][ni][2], acc[mi][ni][3]);
        }
}

// ---- persistent fused edge MLP (R13 core): ldmatrix frags, W2 resident,
// W3 ping-pong streamed (constant data: only the non-resident pair reloads).
// edge_index is int32 on the wire. src=ei[i], dst=ei[E+i]. Degree fused in scatter.
__global__ __launch_bounds__(THREADS, 1) void edge_kernel(const int* __restrict__ ei,
                                                          const float* __restrict__ b3) {
    extern __shared__ char smem[];
    uint32_t sb = smem_u32(smem);
    int t = threadIdx.x, lane = t & 31, wid = t >> 5;

    // ---- load W2 into 4 swizzled panels (once per CTA) ----
#pragma unroll
    for (int j = 0; j < 16; ++j) {
        int item = j * THREADS + t;              // 8192 items
        int r = item >> 5, p = (item >> 3) & 3, ch = item & 7;
        uint4 w = *(const uint4*)(d_W2h + (size_t)r * 256 + p * 64 + ch * 8);
        *(uint4*)(smem + OFF_W2 + p * 32768 + SWZ(r * 128 + ch * 16)) = w;
    }

    // W3 chunk-stream item coords (per thread, 2 items of 16B per chunk)
    int w3n0 = t >> 3, w3ch = t & 7;
    int w3n1 = (512 + t) >> 3;
    uint32_t w3soff0 = SWZ(w3n0 * 128 + w3ch * 16);
    uint32_t w3soff1 = SWZ(w3n1 * 128 + w3ch * 16);

    // ---- preload W3 pair 0 (chunks 0,1) into the ping-pong buffer ----
#pragma unroll
    for (int s = 0; s < 2; ++s) {
        *(uint4*)(smem + OFF_W3 + s * 16384 + w3soff0) =
            *(const uint4*)(d_W3h + (size_t)w3n0 * 256 + s * 64 + w3ch * 8);
        *(uint4*)(smem + OFF_W3 + s * 16384 + w3soff1) =
            *(const uint4*)(d_W3h + (size_t)w3n1 * 256 + s * 64 + w3ch * 8);
    }

    int warpM = wid >> 2, warpN = wid & 3;       // 4x4 warp grid
    int qr = lane >> 2, qc = lane & 3;
    uint32_t xorl = (uint32_t)(lane & 7) << 4;   // SW128 XOR for ldmatrix rows
    uint32_t xorq = (uint32_t)qr << 4;           // SW128 XOR for epilogue rows
    const __half2 z2 = __float2half2_rn(0.f);

    // ldmatrix per-lane bases
    uint32_t aColHi = ((lane >> 4) & 1) * 16;
    uint32_t aBase  = sb + OFF_H1 + (warpM * 32 + (lane & 15)) * 128;
    uint32_t bRowOff = (uint32_t)((lane & 7) + ((lane >> 4) << 3));
    uint32_t bColHi  = ((lane >> 3) & 1) * 16;
    uint32_t b2Base  = sb + OFF_W2 + (warpN * 64 + bRowOff) * 128;
    uint32_t b3Base  = sb + OFF_W3 + (warpN * 32 + bRowOff) * 128;

    int pair = 0;    // which chunk pair the W3 buffer currently holds

    for (int tile = blockIdx.x; tile < TILES; tile += gridDim.x) {
        int e0 = tile * EPB;
        __syncthreads();   // h1 free + preloaded/staged W3 visible

        // ---- gather + layer-1 -> h1 panels (fp16, swizzled), 128 edges ----
#pragma unroll
        for (int j = 0; j < 8; ++j) {
            int item = j * THREADS + t;          // 4096 items
            int e = item >> 5, p = (item >> 3) & 3, ch = item & 7;
            int sidx = __ldg(ei + e0 + e);
            int didx = __ldg(ei + Ee + e0 + e);
            uint4 uu = *(const uint4*)(d_UVh + (size_t)didx * 512 + p * 64 + ch * 8);
            uint4 vv = *(const uint4*)(d_UVh + (size_t)sidx * 512 + 256 + p * 64 + ch * 8);
            const __half2* up = (const __half2*)&uu;
            const __half2* vp = (const __half2*)&vv;
            __half2 r[4];
#pragma unroll
            for (int q = 0; q < 4; ++q)
                r[q] = __hmax2(__hadd2(__hadd2(up[q], vp[q]), d_b1h2[p * 32 + ch * 4 + q]), z2);
            *(uint4*)(smem + OFF_H1 + p * 16384 + SWZ(e * 128 + ch * 16)) = *(uint4*)r;
        }
        __syncthreads();

        // ---- layer 2: [128,256] = h1 @ W2^T, warp tile 32x64, ldmatrix frags ----
        float acc[2][8][4] = {};
        {
#pragma unroll
            for (int ks = 0; ks < 16; ++ks) {
                int kg = ks * 16, p = kg >> 6;
                uint32_t kp2 = (uint32_t)((kg & 63) * 2);
                uint32_t a0[4], a1[4];
                uint32_t acb = (kp2 + aColHi) ^ xorl;
                ldsm4(a0, aBase + p * 16384 + acb);
                ldsm4(a1, aBase + 2048 + p * 16384 + acb);
                uint32_t wb = b2Base + p * 32768 + ((kp2 + bColHi) ^ xorl);
#pragma unroll
                for (int ni2 = 0; ni2 < 4; ++ni2) {
                    uint32_t bb[4];
                    ldsm4(bb, wb + ni2 * 2048);
                    mma16(acc[0][2 * ni2],     a0, bb);
                    mma16(acc[1][2 * ni2],     a1, bb);
                    mma16(acc[0][2 * ni2 + 1], a0, bb + 2);
                    mma16(acc[1][2 * ni2 + 1], a1, bb + 2);
                }
            }
        }

        // prefetch the OTHER W3 pair (LDG into regs; STS after part-A sync)
        int otherPair = pair ^ 1;
        uint4 wA0 = *(const uint4*)(d_W3h + (size_t)w3n0 * 256 + (otherPair * 2 + 0) * 64 + w3ch * 8);
        uint4 wA1 = *(const uint4*)(d_W3h + (size_t)w3n1 * 256 + (otherPair * 2 + 0) * 64 + w3ch * 8);
        uint4 wB0 = *(const uint4*)(d_W3h + (size_t)w3n0 * 256 + (otherPair * 2 + 1) * 64 + w3ch * 8);
        uint4 wB1 = *(const uint4*)(d_W3h + (size_t)w3n1 * 256 + (otherPair * 2 + 1) * 64 + w3ch * 8);

        __syncthreads();   // all layer-2 reads of h1 done

        // ---- bias + relu in half2: h2 over h1 panels ----
        {
            int rB = warpM * 32, cB = warpN * 64;
#pragma unroll
            for (int mi = 0; mi < 2; ++mi) {
                int r0 = rB + mi * 16 + qr, r1 = r0 + 8;
#pragma unroll
                for (int ni = 0; ni < 8; ++ni) {
                    int c0 = cB + ni * 8 + 2 * qc;
                    int p = c0 >> 6, cp = c0 & 63;
                    __half2 bh = d_b2h2[c0 >> 1];
                    char* hp = smem + OFF_H1 + p * 16384;
                    uint32_t coff = ((uint32_t)(cp * 2)) ^ xorq;
                    __half2 lo = __floats2half2_rn(acc[mi][ni][0], acc[mi][ni][1]);
                    __half2 hi = __floats2half2_rn(acc[mi][ni][2], acc[mi][ni][3]);
                    *(__half2*)(hp + r0 * 128 + coff) = __hmax2(__hadd2(lo, bh), z2);
                    *(__half2*)(hp + r1 * 128 + coff) = __hmax2(__hadd2(hi, bh), z2);
                }
            }
        }
        __syncthreads();   // h2 visible; W3 buffer still holds current pair

        // ---- layer 3: [128,128] = h2 @ W3^T, warp tile 32x32, ping-pong pairs ----
        float acc3[2][4][4] = {};
#pragma unroll
        for (int part = 0; part < 2; ++part) {
            int basec = (part == 0 ? pair : otherPair) * 2;
#pragma unroll
            for (int s = 0; s < 2; ++s) {
                uint32_t wb3 = b3Base + s * 16384;
                uint32_t ab3 = aBase + (basec + s) * 16384;
#pragma unroll
                for (int ks = 0; ks < 4; ++ks) {
                    uint32_t kp2 = (uint32_t)(ks * 32);
                    uint32_t a0[4], a1[4];
                    uint32_t acb = (kp2 + aColHi) ^ xorl;
                    ldsm4(a0, ab3 + acb);
                    ldsm4(a1, ab3 + 2048 + acb);
                    uint32_t wb = wb3 + ((kp2 + bColHi) ^ xorl);
#pragma unroll
                    for (int ni2 = 0; ni2 < 2; ++ni2) {
                        uint32_t bb[4];
                        ldsm4(bb, wb + ni2 * 2048);
                        mma16(acc3[0][2 * ni2],     a0, bb);
                        mma16(acc3[1][2 * ni2],     a1, bb);
                        mma16(acc3[0][2 * ni2 + 1], a0, bb + 2);
                        mma16(acc3[1][2 * ni2 + 1], a1, bb + 2);
                    }
                }
            }
            if (part == 0) {
                __syncthreads();   // current pair consumed
                *(uint4*)(smem + OFF_W3 + w3soff0) = wA0;
                *(uint4*)(smem + OFF_W3 + w3soff1) = wA1;
                *(uint4*)(smem + OFF_W3 + 16384 + w3soff0) = wB0;
                *(uint4*)(smem + OFF_W3 + 16384 + w3soff1) = wB1;
                __syncthreads();   // other pair staged
            }
        }
        pair = otherPair;   // buffer now holds the other pair for the next tile

        // ---- scatter: bias + vector atomics into d_sum[dst]; fused degree count ----
        int rB = warpM * 32, cB3 = warpN * 32;
#pragma unroll
        for (int mi = 0; mi < 2; ++mi) {
            int r0 = rB + mi * 16 + qr;
            int d0 = __ldg(ei + Ee + e0 + r0);
            int d1 = __ldg(ei + Ee + e0 + r0 + 8);
            float* p0b = d_sum + (size_t)d0 * Ff;
            float* p1b = d_sum + (size_t)d1 * Ff;
            if (warpN == 0 && qc == 0) {
                asm volatile("red.global.add.f32 [%0], %1;" :: "l"(d_cnt + d0), "f"(1.0f) : "memory");
                asm volatile("red.global.add.f32 [%0], %1;" :: "l"(d_cnt + d1), "f"(1.0f) : "memory");
            }
#pragma unroll
            for (int ni = 0; ni < 4; ++ni) {
                int c0 = cB3 + ni * 8 + 2 * qc;
                float2 bb = __ldg((const float2*)(b3 + c0));
                asm volatile("red.global.add.v2.f32 [%0], {%1,%2};"
                             :: "l"(p0b + c0), "f"(acc3[mi][ni][0] + bb.x),
                                "f"(acc3[mi][ni][1] + bb.y) : "memory");
                asm volatile("red.global.add.v2.f32 [%0], {%1,%2};"
                             :: "l"(p1b + c0), "f"(acc3[mi][ni][2] + bb.x),
                                "f"(acc3[mi][ni][3] + bb.y) : "memory");
            }
        }
    }
}

__global__ void final_kernel(float* __restrict__ out) {
    int i = blockIdx.x * blockDim.x + threadIdx.x;
    if (i < Nn * Ff / 4) {
        int n = i >> 5;
        float c = fmaxf(d_cnt[n], 1.0f);
        float4 v = ((const float4*)d_sum)[i];
        ((float4*)out)[i] = make_float4(tanhf(v.x / c), tanhf(v.y / c),
                                        tanhf(v.z / c), tanhf(v.w / c));
    }
}

// ---------------------------------------------------------------
extern "C" void kernel_launch(void* const* d_in, const int* in_sizes, int n_in,
                              void* d_out, int out_size) {
    const float* x  = (const float*)d_in[0];
    const int*   ei = (const int*)d_in[1];     // int32 (JAX x64 disabled)
    const float* W1 = (const float*)d_in[2];
    const float* b1 = (const float*)d_in[3];
    const float* g1 = (const float*)d_in[4];
    const float* be1 = (const float*)d_in[5];
    const float* rm1 = (const float*)d_in[6];
    const float* rv1 = (const float*)d_in[7];
    const float* W2 = (const float*)d_in[8];
    const float* b2 = (const float*)d_in[9];
    const float* g2 = (const float*)d_in[10];
    const float* be2 = (const float*)d_in[11];
    const float* rm2 = (const float*)d_in[12];
    const float* rv2 = (const float*)d_in[13];
    const float* W3 = (const float*)d_in[14];
    const float* b3 = (const float*)d_in[15];
    float* out = (float*)d_out;

    cudaFuncSetAttribute(uv_gemm, cudaFuncAttributeMaxDynamicSharedMemorySize, UVSMEM);
    cudaFuncSetAttribute(edge_kernel, cudaFuncAttributeMaxDynamicSharedMemorySize, EDGESMEM);

    prep_kernel<<<(Nn * Ff / 4 + 255) / 256, 256>>>(W1, b1, g1, be1, rm1, rv1,
                                                    W2, b2, g2, be2, rm2, rv2, W3);
    uv_gemm<<<dim3((Nn + 63) / 64, 2), 256, UVSMEM>>>(x);
    edge_kernel<<<EDGE_GRID, THREADS, EDGESMEM>>>(ei, b3);
    final_kernel<<<(Nn * Ff / 4 + 255) / 256, 256>>>(out);
}

// round 17
// speedup vs baseline: 1.0582x; 1.0045x over previous
#include <cuda_runtime.h>
#include <cuda_fp16.h>
#include <math.h>
#include <stdint.h>

#define Nn 20000
#define Ee 320000
#define Ff 128
#define EPS 1e-5f

#define EPB 128
#define THREADS 512
#define TILES (Ee / EPB)       // 2500
#define EDGE_GRID 148

// edge kernel smem layout (bytes)
#define OFF_W2 0               // 4 panels x 32768 (256 rows x 128B, SW128) = 128K resident
#define OFF_H1 131072          // 4 panels x 16384 (128 rows x 128B) = 64K (h1, then h2)
#define OFF_W3 196608          // 2 chunk buffers x 16384 (128 rows x 128B), ping-pong pairs
#define EDGESMEM 229376

#define SWZ(x) ((x) ^ (((x) >> 3) & 0x70))

// ---- device scratch ----
__device__ __half  d_Ch[512 * 128];          // folded layer-1 weights (fp16)
__device__ __half  d_W2h[256 * 256];
__device__ __half  d_W3h[128 * 256];
__device__ __half2 d_b2h2[128];
__device__ __half2 d_b1h2[128];
__device__ __half  d_UVh[(size_t)Nn * 512];
__device__ float   d_sum[(size_t)Nn * Ff];
__device__ float   d_cnt[Nn];

__device__ __forceinline__ void mma16(float d[4], const uint32_t a[4], const uint32_t b[2]) {
    asm volatile(
        "mma.sync.aligned.m16n8k16.row.col.f32.f16.f16.f32 "
        "{%0,%1,%2,%3}, {%4,%5,%6,%7}, {%8,%9}, {%0,%1,%2,%3};\n"
        : "+f"(d[0]), "+f"(d[1]), "+f"(d[2]), "+f"(d[3])
        : "r"(a[0]), "r"(a[1]), "r"(a[2]), "r"(a[3]), "r"(b[0]), "r"(b[1]));
}
__device__ __forceinline__ void ldsm4(uint32_t r[4], uint32_t addr) {
    asm volatile("ldmatrix.sync.aligned.m8n8.x4.shared.b16 {%0,%1,%2,%3}, [%4];"
                 : "=r"(r[0]), "=r"(r[1]), "=r"(r[2]), "=r"(r[3]) : "r"(addr));
}
__device__ __forceinline__ uint32_t smem_u32(const void* p) {
    uint32_t a;
    asm("{ .reg .u64 t; cvta.to.shared.u64 t, %1; cvt.u32.u64 %0, t; }" : "=r"(a) : "l"(p));
    return a;
}
__device__ __forceinline__ float tanh_fast(float x) {
    float y;
    asm("tanh.approx.f32 %0, %1;" : "=f"(y) : "f"(x));
    return y;
}
__device__ __forceinline__ float rcp_fast(float x) {
    float y;
    asm("rcp.approx.f32 %0, %1;" : "=f"(y) : "f"(x));
    return y;
}

// ---------------------------------------------------------------
// prep + zero fused: grid covers max(weight work, zero work)
__global__ void prep_kernel(const float* __restrict__ W1, const float* __restrict__ b1,
                            const float* __restrict__ g1, const float* __restrict__ be1,
                            const float* __restrict__ rm1, const float* __restrict__ rv1,
                            const float* __restrict__ W2, const float* __restrict__ b2,
                            const float* __restrict__ g2, const float* __restrict__ be2,
                            const float* __restrict__ rm2, const float* __restrict__ rv2,
                            const float* __restrict__ W3) {
    int i = blockIdx.x * blockDim.x + threadIdx.x;
    if (i < Nn * Ff / 4) ((float4*)d_sum)[i] = make_float4(0.f, 0.f, 0.f, 0.f);
    if (i < Nn / 4)      ((float4*)d_cnt)[i] = make_float4(0.f, 0.f, 0.f, 0.f);
    if (i < 512 * 128) {
        int j = i >> 7, k = i & 127, o = j & 255;
        float s = g1[o] * rsqrtf(rv1[o] + EPS);
        float w = (j < 256) ? (W1[o * 256 + k] - W1[o * 256 + 128 + k])
                            : W1[o * 256 + 128 + k];
        d_Ch[i] = __float2half(s * w);
    }
    if (i < 256 * 256) {
        int o = i >> 8;
        float s = g2[o] * rsqrtf(rv2[o] + EPS);
        d_W2h[i] = __float2half(s * W2[i]);
    }
    if (i < 128 * 256) d_W3h[i] = __float2half(W3[i]);
    if (i < 128) {
        int o0 = 2 * i, o1 = 2 * i + 1;
        float s0 = g2[o0] * rsqrtf(rv2[o0] + EPS);
        float s1 = g2[o1] * rsqrtf(rv2[o1] + EPS);
        d_b2h2[i] = __floats2half2_rn(b2[o0] * s0 + (be2[o0] - rm2[o0] * s0),
                                      b2[o1] * s1 + (be2[o1] - rm2[o1] * s1));
        float sa = g1[o0] * rsqrtf(rv1[o0] + EPS);
        float sb = g1[o1] * rsqrtf(rv1[o1] + EPS);
        d_b1h2[i] = __floats2half2_rn(b1[o0] * sa + (be1[o0] - rm1[o0] * sa),
                                      b1[o1] * sb + (be1[o1] - rm1[o1] * sb));
    }
}

// UV = x @ C^T via fp16 mma (fp32 accum). grid (313, 2), 2 CTAs/SM.
#define SXH2 68
#define UVSMEM ((64 + 256) * SXH2 * 4)
__global__ __launch_bounds__(256, 2) void uv_gemm(const float* __restrict__ x) {
    extern __shared__ __half2 smh[];
    __half2* xs2 = smh;                 // [64][SXH2]
    __half2* cs2 = smh + 64 * SXH2;     // [256][SXH2]
    const __half* xsh = (const __half*)xs2;
    const __half* csh = (const __half*)cs2;
    int t = threadIdx.x, lane = t & 31, wid = t >> 5;
    int rowBase = blockIdx.x * 64;
    int cb = blockIdx.y * 256;

#pragma unroll
    for (int j = 0; j < 8; ++j) {
        int idx = t + j * 256;
        int r = idx >> 5, c4 = idx & 31;
        int gr = rowBase + r;
        float4 v = (gr < Nn) ? *(const float4*)(x + (size_t)gr * 128 + c4 * 4)
                             : make_float4(0.f, 0.f, 0.f, 0.f);
        xs2[r * SXH2 + c4 * 2]     = __floats2half2_rn(v.x, v.y);
        xs2[r * SXH2 + c4 * 2 + 1] = __floats2half2_rn(v.z, v.w);
    }
#pragma unroll
    for (int j = 0; j < 16; ++j) {
        int idx = t + j * 256;
        int n = idx >> 4, c8 = idx & 15;
        uint4 w = *(const uint4*)(d_Ch + (size_t)(cb + n) * 128 + c8 * 8);
        *(uint4*)((__half*)(cs2 + n * SXH2) + c8 * 8) = w;
    }
    __syncthreads();

    int warpM = wid >> 2, warpN = wid & 3;
    int rB = warpM * 32, cB = warpN * 64;
    int qr = lane >> 2, qc = lane & 3;

    float acc[2][8][4] = {};
#pragma unroll
    for (int ks = 0; ks < 8; ++ks) {
        int kg = ks * 16;
        uint32_t a[2][4];
#pragma unroll
        for (int mi = 0; mi < 2; ++mi) {
            int r0 = rB + mi * 16 + qr;
            a[mi][0] = *(const uint32_t*)(xsh + r0 * (2 * SXH2) + kg + 2 * qc);
            a[mi][1] = *(const uint32_t*)(xsh + (r0 + 8) * (2 * SXH2) + kg + 2 * qc);
            a[mi][2] = *(const uint32_t*)(xsh + r0 * (2 * SXH2) + kg + 8 + 2 * qc);
            a[mi][3] = *(const uint32_t*)(xsh + (r0 + 8) * (2 * SXH2) + kg + 8 + 2 * qc);
        }
#pragma unroll
        for (int ni = 0; ni < 8; ++ni) {
            int n0 = cB + ni * 8 + qr;
            uint32_t b[2];
            b[0] = *(const uint32_t*)(csh + n0 * (2 * SXH2) + kg + 2 * qc);
            b[1] = *(const uint32_t*)(csh + n0 * (2 * SXH2) + kg + 8 + 2 * qc);
            mma16(acc[0][ni], a[0], b);
            mma16(acc[1][ni], a[1], b);
        }
    }
#pragma unroll
    for (int mi = 0; mi < 2; ++mi)
#pragma unroll
        for (int ni = 0; ni < 8; ++ni) {
            int r0 = rowBase + rB + mi * 16 + qr;
            int c0 = cb + cB + ni * 8 + 2 * qc;
            if (r0 < Nn)
                *(__half2*)(d_UVh + (size_t)r0 * 512 + c0) =
                    __floats2half2_rn(acc[mi][ni][0], acc[mi][ni][1]);
            if (r0 + 8 < Nn)
                *(__half2*)(d_UVh + (size_t)(r0 + 8) * 512 + c0) =
                    __floats2half2_rn(acc[mi][ni][2], acc[mi][ni][3]);
        }
}

// ---- persistent fused edge MLP: ldmatrix frags, W2 resident,
// W3 ping-pong streamed (constant data: only the non-resident pair reloads).
// edge_index is int32 on the wire. src=ei[i], dst=ei[E+i]. Degree fused in scatter.
__global__ __launch_bounds__(THREADS, 1) void edge_kernel(const int* __restrict__ ei,
                                                          const float* __restrict__ b3) {
    extern __shared__ char smem[];
    uint32_t sb = smem_u32(smem);
    int t = threadIdx.x, lane = t & 31, wid = t >> 5;

    // ---- load W2 into 4 swizzled panels (once per CTA) ----
#pragma unroll
    for (int j = 0; j < 16; ++j) {
        int item = j * THREADS + t;              // 8192 items
        int r = item >> 5, p = (item >> 3) & 3, ch = item & 7;
        uint4 w = *(const uint4*)(d_W2h + (size_t)r * 256 + p * 64 + ch * 8);
        *(uint4*)(smem + OFF_W2 + p * 32768 + SWZ(r * 128 + ch * 16)) = w;
    }

    // W3 chunk-stream item coords (per thread, 2 items of 16B per chunk)
    int w3n0 = t >> 3, w3ch = t & 7;
    int w3n1 = (512 + t) >> 3;
    uint32_t w3soff0 = SWZ(w3n0 * 128 + w3ch * 16);
    uint32_t w3soff1 = SWZ(w3n1 * 128 + w3ch * 16);

    // ---- preload W3 pair 0 (chunks 0,1) into the ping-pong buffer ----
#pragma unroll
    for (int s = 0; s < 2; ++s) {
        *(uint4*)(smem + OFF_W3 + s * 16384 + w3soff0) =
            *(const uint4*)(d_W3h + (size_t)w3n0 * 256 + s * 64 + w3ch * 8);
        *(uint4*)(smem + OFF_W3 + s * 16384 + w3soff1) =
            *(const uint4*)(d_W3h + (size_t)w3n1 * 256 + s * 64 + w3ch * 8);
    }

    int warpM = wid >> 2, warpN = wid & 3;       // 4x4 warp grid
    int qr = lane >> 2, qc = lane & 3;
    uint32_t xorl = (uint32_t)(lane & 7) << 4;   // SW128 XOR for ldmatrix rows
    uint32_t xorq = (uint32_t)qr << 4;           // SW128 XOR for epilogue rows
    const __half2 z2 = __float2half2_rn(0.f);

    // ldmatrix per-lane bases
    uint32_t aColHi = ((lane >> 4) & 1) * 16;
    uint32_t aBase  = sb + OFF_H1 + (warpM * 32 + (lane & 15)) * 128;
    uint32_t bRowOff = (uint32_t)((lane & 7) + ((lane >> 4) << 3));
    uint32_t bColHi  = ((lane >> 3) & 1) * 16;
    uint32_t b2Base  = sb + OFF_W2 + (warpN * 64 + bRowOff) * 128;
    uint32_t b3Base  = sb + OFF_W3 + (warpN * 32 + bRowOff) * 128;

    int pair = 0;    // which chunk pair the W3 buffer currently holds

    for (int tile = blockIdx.x; tile < TILES; tile += gridDim.x) {
        int e0 = tile * EPB;
        __syncthreads();   // h1 free + preloaded/staged W3 visible

        // ---- gather + layer-1 -> h1 panels (fp16, swizzled), 128 edges ----
#pragma unroll
        for (int j = 0; j < 8; ++j) {
            int item = j * THREADS + t;          // 4096 items
            int e = item >> 5, p = (item >> 3) & 3, ch = item & 7;
            int sidx = __ldg(ei + e0 + e);
            int didx = __ldg(ei + Ee + e0 + e);
            uint4 uu = *(const uint4*)(d_UVh + (size_t)didx * 512 + p * 64 + ch * 8);
            uint4 vv = *(const uint4*)(d_UVh + (size_t)sidx * 512 + 256 + p * 64 + ch * 8);
            const __half2* up = (const __half2*)&uu;
            const __half2* vp = (const __half2*)&vv;
            __half2 r[4];
#pragma unroll
            for (int q = 0; q < 4; ++q)
                r[q] = __hmax2(__hadd2(__hadd2(up[q], vp[q]), d_b1h2[p * 32 + ch * 4 + q]), z2);
            *(uint4*)(smem + OFF_H1 + p * 16384 + SWZ(e * 128 + ch * 16)) = *(uint4*)r;
        }
        __syncthreads();

        // ---- layer 2: [128,256] = h1 @ W2^T, warp tile 32x64, ldmatrix frags ----
        float acc[2][8][4] = {};
        {
#pragma unroll
            for (int ks = 0; ks < 16; ++ks) {
                int kg = ks * 16, p = kg >> 6;
                uint32_t kp2 = (uint32_t)((kg & 63) * 2);
                uint32_t a0[4], a1[4];
                uint32_t acb = (kp2 + aColHi) ^ xorl;
                ldsm4(a0, aBase + p * 16384 + acb);
                ldsm4(a1, aBase + 2048 + p * 16384 + acb);
                uint32_t wb = b2Base + p * 32768 + ((kp2 + bColHi) ^ xorl);
#pragma unroll
                for (int ni2 = 0; ni2 < 4; ++ni2) {
                    uint32_t bb[4];
                    ldsm4(bb, wb + ni2 * 2048);
                    mma16(acc[0][2 * ni2],     a0, bb);
                    mma16(acc[1][2 * ni2],     a1, bb);
                    mma16(acc[0][2 * ni2 + 1], a0, bb + 2);
                    mma16(acc[1][2 * ni2 + 1], a1, bb + 2);
                }
            }
        }

        // prefetch the OTHER W3 pair (LDG into regs; STS after part-A sync)
        int otherPair = pair ^ 1;
        uint4 wA0 = *(const uint4*)(d_W3h + (size_t)w3n0 * 256 + (otherPair * 2 + 0) * 64 + w3ch * 8);
        uint4 wA1 = *(const uint4*)(d_W3h + (size_t)w3n1 * 256 + (otherPair * 2 + 0) * 64 + w3ch * 8);
        uint4 wB0 = *(const uint4*)(d_W3h + (size_t)w3n0 * 256 + (otherPair * 2 + 1) * 64 + w3ch * 8);
        uint4 wB1 = *(const uint4*)(d_W3h + (size_t)w3n1 * 256 + (otherPair * 2 + 1) * 64 + w3ch * 8);

        __syncthreads();   // all layer-2 reads of h1 done

        // ---- bias + relu in half2: h2 over h1 panels ----
        {
            int rB = warpM * 32, cB = warpN * 64;
#pragma unroll
            for (int mi = 0; mi < 2; ++mi) {
                int r0 = rB + mi * 16 + qr, r1 = r0 + 8;
#pragma unroll
                for (int ni = 0; ni < 8; ++ni) {
                    int c0 = cB + ni * 8 + 2 * qc;
                    int p = c0 >> 6, cp = c0 & 63;
                    __half2 bh = d_b2h2[c0 >> 1];
                    char* hp = smem + OFF_H1 + p * 16384;
                    uint32_t coff = ((uint32_t)(cp * 2)) ^ xorq;
                    __half2 lo = __floats2half2_rn(acc[mi][ni][0], acc[mi][ni][1]);
                    __half2 hi = __floats2half2_rn(acc[mi][ni][2], acc[mi][ni][3]);
                    *(__half2*)(hp + r0 * 128 + coff) = __hmax2(__hadd2(lo, bh), z2);
                    *(__half2*)(hp + r1 * 128 + coff) = __hmax2(__hadd2(hi, bh), z2);
                }
            }
        }
        __syncthreads();   // h2 visible; W3 buffer still holds current pair

        // ---- layer 3: [128,128] = h2 @ W3^T, warp tile 32x32, ping-pong pairs ----
        float acc3[2][4][4] = {};
#pragma unroll
        for (int part = 0; part < 2; ++part) {
            int basec = (part == 0 ? pair : otherPair) * 2;
#pragma unroll
            for (int s = 0; s < 2; ++s) {
                uint32_t wb3 = b3Base + s * 16384;
                uint32_t ab3 = aBase + (basec + s) * 16384;
#pragma unroll
                for (int ks = 0; ks < 4; ++ks) {
                    uint32_t kp2 = (uint32_t)(ks * 32);
                    uint32_t a0[4], a1[4];
                    uint32_t acb = (kp2 + aColHi) ^ xorl;
                    ldsm4(a0, ab3 + acb);
                    ldsm4(a1, ab3 + 2048 + acb);
                    uint32_t wb = wb3 + ((kp2 + bColHi) ^ xorl);
#pragma unroll
                    for (int ni2 = 0; ni2 < 2; ++ni2) {
                        uint32_t bb[4];
                        ldsm4(bb, wb + ni2 * 2048);
                        mma16(acc3[0][2 * ni2],     a0, bb);
                        mma16(acc3[1][2 * ni2],     a1, bb);
                        mma16(acc3[0][2 * ni2 + 1], a0, bb + 2);
                        mma16(acc3[1][2 * ni2 + 1], a1, bb + 2);
                    }
                }
            }
            if (part == 0) {
                __syncthreads();   // current pair consumed
                *(uint4*)(smem + OFF_W3 + w3soff0) = wA0;
                *(uint4*)(smem + OFF_W3 + w3soff1) = wA1;
                *(uint4*)(smem + OFF_W3 + 16384 + w3soff0) = wB0;
                *(uint4*)(smem + OFF_W3 + 16384 + w3soff1) = wB1;
                __syncthreads();   // other pair staged
            }
        }
        pair = otherPair;   // buffer now holds the other pair for the next tile

        // ---- scatter: bias + vector atomics into d_sum[dst]; fused degree count ----
        int rB = warpM * 32, cB3 = warpN * 32;
#pragma unroll
        for (int mi = 0; mi < 2; ++mi) {
            int r0 = rB + mi * 16 + qr;
            int d0 = __ldg(ei + Ee + e0 + r0);
            int d1 = __ldg(ei + Ee + e0 + r0 + 8);
            float* p0b = d_sum + (size_t)d0 * Ff;
            float* p1b = d_sum + (size_t)d1 * Ff;
            if (warpN == 0 && qc == 0) {
                asm volatile("red.global.add.f32 [%0], %1;" :: "l"(d_cnt + d0), "f"(1.0f) : "memory");
                asm volatile("red.global.add.f32 [%0], %1;" :: "l"(d_cnt + d1), "f"(1.0f) : "memory");
            }
#pragma unroll
            for (int ni = 0; ni < 4; ++ni) {
                int c0 = cB3 + ni * 8 + 2 * qc;
                float2 bb = __ldg((const float2*)(b3 + c0));
                asm volatile("red.global.add.v2.f32 [%0], {%1,%2};"
                             :: "l"(p0b + c0), "f"(acc3[mi][ni][0] + bb.x),
                                "f"(acc3[mi][ni][1] + bb.y) : "memory");
                asm volatile("red.global.add.v2.f32 [%0], {%1,%2};"
                             :: "l"(p1b + c0), "f"(acc3[mi][ni][2] + bb.x),
                                "f"(acc3[mi][ni][3] + bb.y) : "memory");
            }
        }
    }
}

__global__ void final_kernel(float* __restrict__ out) {
    int i = blockIdx.x * blockDim.x + threadIdx.x;
    if (i < Nn * Ff / 4) {
        int n = i >> 5;
        float rc = rcp_fast(fmaxf(d_cnt[n], 1.0f));
        float4 v = ((const float4*)d_sum)[i];
        ((float4*)out)[i] = make_float4(tanh_fast(v.x * rc), tanh_fast(v.y * rc),
                                        tanh_fast(v.z * rc), tanh_fast(v.w * rc));
    }
}

// ---------------------------------------------------------------
extern "C" void kernel_launch(void* const* d_in, const int* in_sizes, int n_in,
                              void* d_out, int out_size) {
    const float* x  = (const float*)d_in[0];
    const int*   ei = (const int*)d_in[1];     // int32 (JAX x64 disabled)
    const float* W1 = (const float*)d_in[2];
    const float* b1 = (const float*)d_in[3];
    const float* g1 = (const float*)d_in[4];
    const float* be1 = (const float*)d_in[5];
    const float* rm1 = (const float*)d_in[6];
    const float* rv1 = (const float*)d_in[7];
    const float* W2 = (const float*)d_in[8];
    const float* b2 = (const float*)d_in[9];
    const float* g2 = (const float*)d_in[10];
    const float* be2 = (const float*)d_in[11];
    const float* rm2 = (const float*)d_in[12];
    const float* rv2 = (const float*)d_in[13];
    const float* W3 = (const float*)d_in[14];
    const float* b3 = (const float*)d_in[15];
    float* out = (float*)d_out;

    cudaFuncSetAttribute(uv_gemm, cudaFuncAttributeMaxDynamicSharedMemorySize, UVSMEM);
    cudaFuncSetAttribute(edge_kernel, cudaFuncAttributeMaxDynamicSharedMemorySize, EDGESMEM);

    prep_kernel<<<(Nn * Ff / 4 + 255) / 256, 256>>>(W1, b1, g1, be1, rm1, rv1,
                                                    W2, b2, g2, be2, rm2, rv2, W3);
    uv_gemm<<<dim3((Nn + 63) / 64, 2), 256, UVSMEM>>>(x);
    edge_kernel<<<EDGE_GRID, THREADS, EDGESMEM>>>(ei, b3);
    final_kernel<<<(Nn * Ff / 4 + 255) / 256, 256>>>(out);
}